// round 16
// baseline (speedup 1.0000x reference)
#include <cuda_runtime.h>
#include <cuda_fp16.h>
#include <math.h>
#include <stdint.h>

#define B_      32
#define CIN     128
#define COUT    128
#define HW      128
#define ZD      512
#define EPSV    1e-8f

// ---------------- device scratch ----------------
__device__ float g_mod[B_ * CIN];
__device__ float g_S[COUT * CIN];
__device__ float g_dscale[B_ * COUT];
// weights fp16: [st = tap*2+ihalf][oc][64]
__device__ __align__(256) __half g_wh[18 * 128 * 64];
// x*mod fp16, NHWC: [b][y][x][ic]
__device__ __align__(256) __half g_xh[(size_t)B_ * HW * HW * CIN];

// ---------------- helpers ----------------
__device__ __forceinline__ uint32_t smem_u32(const void* p) {
    uint32_t a;
    asm("{ .reg .u64 t; cvta.to.shared.u64 t, %1; cvt.u32.u64 %0, t; }" : "=r"(a) : "l"(p));
    return a;
}
__device__ __forceinline__ void cpasync16(uint32_t dst, const void* src, int sz) {
    asm volatile("cp.async.cg.shared.global [%0], [%1], 16, %2;"
        :: "r"(dst), "l"(src), "r"(sz) : "memory");
}
#define CP_COMMIT() asm volatile("cp.async.commit_group;" ::: "memory")
#define CP_WAIT4()  asm volatile("cp.async.wait_group 4;" ::: "memory")
#define CP_WAIT2()  asm volatile("cp.async.wait_group 2;" ::: "memory")
#define CP_WAIT1()  asm volatile("cp.async.wait_group 1;" ::: "memory")
#define CP_WAIT0()  asm volatile("cp.async.wait_group 0;" ::: "memory")

__device__ __forceinline__ void ldsm_x4(uint32_t a[4], uint32_t addr) {
    asm volatile("ldmatrix.sync.aligned.m8n8.x4.shared.b16 {%0,%1,%2,%3}, [%4];"
        : "=r"(a[0]), "=r"(a[1]), "=r"(a[2]), "=r"(a[3]) : "r"(addr));
}
__device__ __forceinline__ void mma16816(float d[4], const uint32_t a[4], const uint32_t b[2]) {
    asm volatile("mma.sync.aligned.m16n8k16.row.col.f32.f16.f16.f32 "
        "{%0,%1,%2,%3}, {%4,%5,%6,%7}, {%8,%9}, {%0,%1,%2,%3};"
        : "+f"(d[0]), "+f"(d[1]), "+f"(d[2]), "+f"(d[3])
        : "r"(a[0]), "r"(a[1]), "r"(a[2]), "r"(a[3]), "r"(b[0]), "r"(b[1]));
}
__device__ __forceinline__ float mishf(float v) {
    return v * tanhf(log1pf(expf(v)));
}

// ---------------- pre-kernels ----------------
__global__ void style_kernel(const float* __restrict__ z,
                             const float* __restrict__ Wsty,
                             const float* __restrict__ bsty) {
    int b = blockIdx.x, i = threadIdx.x;
    __shared__ float zs[ZD];
    for (int k = threadIdx.x; k < ZD; k += blockDim.x) zs[k] = z[b * ZD + k];
    __syncthreads();
    float s = bsty[i];
    const float* wr = Wsty + i * ZD;
    #pragma unroll 4
    for (int k = 0; k < ZD; k++) s += zs[k] * wr[k];
    g_mod[b * CIN + i] = s + 1.0f;
}

__global__ void ssum_kernel(const float* __restrict__ w) {
    int o = blockIdx.x, i = threadIdx.x;
    const float* p = w + (o * CIN + i) * 9;
    float s = 0.f;
    #pragma unroll
    for (int k = 0; k < 9; k++) s += p[k] * p[k];
    g_S[o * CIN + i] = s;
}

__global__ void dscale_kernel() {
    int pair = blockIdx.x * 8 + (threadIdx.x >> 5);  // 0..4095
    int b = pair >> 7, o = pair & 127;
    int lane = threadIdx.x & 31;
    const float* m = g_mod + b * CIN;
    const float* s = g_S + o * CIN;
    float acc = 0.f;
    #pragma unroll
    for (int q = 0; q < 4; q++) {
        int i = q * 32 + lane;
        float mv = m[i];
        acc += mv * mv * s[i];
    }
    #pragma unroll
    for (int off = 16; off; off >>= 1) acc += __shfl_xor_sync(0xffffffffu, acc, off);
    if (lane == 0) g_dscale[pair] = rsqrtf(acc + EPSV);
}

__global__ void wcvt_kernel(const float* __restrict__ w) {
    int idx = blockIdx.x * 512 + threadIdx.x;      // 0..147455
    int j   = idx & 63;
    int oc  = (idx >> 6) & 127;
    int st  = idx >> 13;
    int ih  = st & 1;
    int tap = st >> 1;
    g_wh[idx] = __float2half_rn(w[(oc * CIN + (ih * 64 + j)) * 9 + tap]);
}

__global__ void xcvt_kernel(const float* __restrict__ x) {
    extern __shared__ float sm[];   // 128 * 133
    int b = blockIdx.x >> 7;
    int y = blockIdx.x & 127;
    #pragma unroll
    for (int i = 0; i < 16; i++) {
        int idx4 = i * 256 + threadIdx.x;
        int ic = idx4 >> 5;
        int x4 = (idx4 & 31) * 4;
        float4 v = *(const float4*)(x + (((size_t)(b * CIN + ic)) * HW + y) * HW + x4);
        float m = g_mod[b * CIN + ic];
        float* d = sm + ic * 133 + x4;
        d[0] = v.x * m; d[1] = v.y * m; d[2] = v.z * m; d[3] = v.w * m;
    }
    __syncthreads();
    int xc = threadIdx.x >> 1;
    int ih = threadIdx.x & 1;
    size_t o = (((size_t)(b * HW + y)) * HW + xc) * CIN + ih * 64;
    __half2* oh = (__half2*)(g_xh + o);
    #pragma unroll
    for (int q = 0; q < 32; q++) {
        float v0 = sm[(ih * 64 + 2 * q) * 133 + xc];
        float v1 = sm[(ih * 64 + 2 * q + 1) * 133 + xc];
        oh[q] = __floats2half2_rn(v0, v1);
    }
}

// ---------------- main conv: B-resident fp16 mma.sync ----------------
// CTA = (b, 2 rows, oc half). D[64 oc x 256 px], K = 18 stages of 64.
// B resident: 4 input rows x 130 xc x 2 ih = 1040 rows of 128B (133KB).
// A: 4-buffer prefetch ring, 8KB/stage.
#define B_BYTES  133120
#define OFF_A    133120
#define SM_TOTAL (133120 + 4 * 8192)   // 165888
#define SWZ(row, cb) ((cb) ^ (((row) & 7) << 4))

__global__ void __launch_bounds__(256, 1)
conv_mma_kernel(float* __restrict__ out) {
    extern __shared__ __align__(1024) unsigned char smem[];
    const uint32_t sb = smem_u32(smem);
    const int t   = threadIdx.x;
    const int wid = t >> 5;
    const int lid = t & 31;
    const int bx  = blockIdx.x;
    const int b   = bx >> 7;
    const int y0  = ((bx >> 1) & 63) << 1;
    const int ocb = (bx & 1) * 64;

    const int oc0 = (wid & 1) * 32;   // local oc block (32 of 64)
    const int n0  = (wid >> 1) * 64;  // px block (64 of 256)

    float d[2][8][4];
    #pragma unroll
    for (int mi = 0; mi < 2; mi++)
        #pragma unroll
        for (int ni = 0; ni < 8; ni++)
            #pragma unroll
            for (int j = 0; j < 4; j++) d[mi][ni][j] = 0.f;

    // per-thread B ldsm row bases (invariant across stages): pxr = py*130 + xc0
    int pxr[4];
    #pragma unroll
    for (int nj = 0; nj < 4; nj++) {
        int brow = n0 + nj * 16 + ((lid >> 4) & 1) * 8 + (lid & 7);   // px 0..255
        pxr[nj] = (brow >> 7) * 130 + (brow & 127);
    }

    auto load_Brows = [&](int y_lo, int n_rows) {
        int total = n_rows * 130 * 2 * 8;          // cp16 count
        int rows  = n_rows * 130;
        for (int e = t; e < total; e += 256) {
            int g   = e & 7;
            int rl  = e >> 3;                      // 0 .. 2*rows-1
            int ih  = (rl >= rows) ? 1 : 0;
            int rem = rl - ih * rows;
            int y   = y_lo + rem / 130;
            int xc  = rem % 130;
            int rid = ih * 520 + y * 130 + xc;
            int gy = y0 - 1 + y, gx = xc - 1;
            bool ok = (unsigned)gy < (unsigned)HW && (unsigned)gx < (unsigned)HW;
            const __half* src = g_xh
                + (((size_t)(b * HW + (ok ? gy : 0))) * HW + (ok ? gx : 0)) * CIN + ih * 64 + g * 8;
            cpasync16(sb + rid * 128 + SWZ(rid, g * 16), src, ok ? 16 : 0);
        }
    };

    auto load_A = [&](int s) {
        uint32_t bufo = OFF_A + (uint32_t)(s & 3) * 8192;
        #pragma unroll
        for (int i = 0; i < 2; i++) {
            int e = i * 256 + t;                   // 0..511
            int row = e >> 3, g = e & 7;
            const __half* src = g_wh + (size_t)s * 8192 + (ocb + row) * 64 + g * 8;
            cpasync16(sb + bufo + row * 128 + SWZ(row, g * 16), src, 16);
        }
    };

    // prologue: BG0(rows 0,1), A0, A1, A2, BG1(row 2), BG2(row 3)
    load_Brows(0, 2); CP_COMMIT();
    load_A(0);        CP_COMMIT();
    load_A(1);        CP_COMMIT();
    load_A(2);        CP_COMMIT();
    load_Brows(2, 1); CP_COMMIT();
    load_Brows(3, 1); CP_COMMIT();

    for (int s = 0; s < 18; s++) {
        if (s < 3)       { CP_WAIT4(); }
        else if (s < 16) { CP_WAIT2(); }
        else if (s == 16){ CP_WAIT1(); }
        else             { CP_WAIT0(); }
        __syncthreads();
        if (s + 3 < 18) { load_A(s + 3); CP_COMMIT(); }

        const int tap = s >> 1;
        const int ih  = s & 1;
        const int ky  = tap / 3;
        const int kx  = tap - ky * 3;
        const int soff = ih * 520 + ky * 130 + kx;
        const uint32_t abase = sb + OFF_A + (uint32_t)(s & 3) * 8192;

        #pragma unroll
        for (int k16 = 0; k16 < 4; k16++) {
            uint32_t a[2][4];
            {
                const uint32_t acb = (uint32_t)k16 * 32 + ((lid >> 4) & 1) * 16;
                #pragma unroll
                for (int mi = 0; mi < 2; mi++) {
                    uint32_t row = oc0 + mi * 16 + (lid & 7) + ((lid >> 3) & 1) * 8;
                    ldsm_x4(a[mi], abase + row * 128 + SWZ(row, acb));
                }
            }
            const uint32_t bcb = (uint32_t)k16 * 32 + ((lid >> 3) & 1) * 16;
            #pragma unroll
            for (int nj = 0; nj < 4; nj++) {
                uint32_t rid = (uint32_t)(soff + pxr[nj]);
                uint32_t b4[4];
                ldsm_x4(b4, sb + rid * 128 + SWZ(rid, bcb));
                mma16816(d[0][2 * nj + 0], a[0], b4 + 0);
                mma16816(d[1][2 * nj + 0], a[1], b4 + 0);
                mma16816(d[0][2 * nj + 1], a[0], b4 + 2);
                mma16816(d[1][2 * nj + 1], a[1], b4 + 2);
            }
        }
    }
    __syncthreads();

    // ---- epilogue: dscale * mish, transpose through smem, write out ----
    float* ep = (float*)smem;        // [256 px][72]
    float dsc[2][2];
    #pragma unroll
    for (int mi = 0; mi < 2; mi++) {
        dsc[mi][0] = g_dscale[b * COUT + ocb + oc0 + mi * 16 + (lid >> 2)];
        dsc[mi][1] = g_dscale[b * COUT + ocb + oc0 + mi * 16 + (lid >> 2) + 8];
    }
    #pragma unroll
    for (int mi = 0; mi < 2; mi++) {
        #pragma unroll
        for (int ni = 0; ni < 8; ni++) {
            #pragma unroll
            for (int j = 0; j < 4; j++) {
                int oc = oc0 + mi * 16 + (lid >> 2) + ((j >> 1) ? 8 : 0);
                int px = n0 + ni * 8 + (lid & 3) * 2 + (j & 1);
                ep[px * 72 + oc] = mishf(d[mi][ni][j] * dsc[mi][(j >> 1)]);
            }
        }
    }
    __syncthreads();

    // 256 threads: oc2 = t&63 (local), slot = t>>6 -> row r = slot>>1, half h = slot&1
    const int oc2  = t & 63;
    const int slot = t >> 6;
    const int r    = slot >> 1;
    const int h    = slot & 1;
    float* dst = out + (((size_t)(b * COUT + ocb + oc2)) * HW + (y0 + r)) * HW + h * 64;
    #pragma unroll
    for (int g = 0; g < 16; g++) {
        int px = r * 128 + h * 64 + g * 4;
        float4 v;
        v.x = ep[(px + 0) * 72 + oc2];
        v.y = ep[(px + 1) * 72 + oc2];
        v.z = ep[(px + 2) * 72 + oc2];
        v.w = ep[(px + 3) * 72 + oc2];
        *(float4*)(dst + g * 4) = v;
    }
}

// ---------------- launch ----------------
extern "C" void kernel_launch(void* const* d_in, const int* in_sizes, int n_in,
                              void* d_out, int out_size) {
    const float* x    = (const float*)d_in[0];
    const float* z    = (const float*)d_in[1];
    const float* w    = (const float*)d_in[2];
    const float* Wsty = (const float*)d_in[3];
    const float* bsty = (const float*)d_in[4];
    float* out = (float*)d_out;

    cudaFuncSetAttribute(conv_mma_kernel, cudaFuncAttributeMaxDynamicSharedMemorySize, SM_TOTAL);
    cudaFuncSetAttribute(xcvt_kernel, cudaFuncAttributeMaxDynamicSharedMemorySize, 128 * 133 * 4);

    style_kernel<<<B_, CIN>>>(z, Wsty, bsty);
    ssum_kernel<<<COUT, CIN>>>(w);
    dscale_kernel<<<512, 256>>>();
    wcvt_kernel<<<288, 512>>>(w);
    xcvt_kernel<<<B_ * HW, 256, 128 * 133 * 4>>>(x);
    conv_mma_kernel<<<B_ * 128, 256, SM_TOTAL>>>(out);
}

// round 17
// speedup vs baseline: 1.1223x; 1.1223x over previous
#include <cuda_runtime.h>
#include <cuda_fp16.h>
#include <math.h>
#include <stdint.h>

#define B_      32
#define CIN     128
#define COUT    128
#define HW      128
#define ZD      512
#define EPSV    1e-8f

// ---------------- device scratch ----------------
__device__ float g_mod[B_ * CIN];
__device__ float g_S[COUT * CIN];
__device__ float g_dscale[B_ * COUT];
// weights fp16: [st = tap*2+ihalf][oc][64]
__device__ __align__(256) __half g_wh[18 * 128 * 64];
// x*mod fp16, NHWC: [b][y][x][ic]
__device__ __align__(256) __half g_xh[(size_t)B_ * HW * HW * CIN];

// ---------------- helpers ----------------
__device__ __forceinline__ uint32_t smem_u32(const void* p) {
    uint32_t a;
    asm("{ .reg .u64 t; cvta.to.shared.u64 t, %1; cvt.u32.u64 %0, t; }" : "=r"(a) : "l"(p));
    return a;
}
__device__ __forceinline__ void cpasync16(uint32_t dst, const void* src, int sz) {
    asm volatile("cp.async.cg.shared.global [%0], [%1], 16, %2;"
        :: "r"(dst), "l"(src), "r"(sz) : "memory");
}
#define CP_COMMIT() asm volatile("cp.async.commit_group;" ::: "memory")
#define CP_WAIT2()  asm volatile("cp.async.wait_group 2;" ::: "memory")
#define CP_WAIT1()  asm volatile("cp.async.wait_group 1;" ::: "memory")
#define CP_WAIT0()  asm volatile("cp.async.wait_group 0;" ::: "memory")

__device__ __forceinline__ void ldsm_x4(uint32_t a[4], uint32_t addr) {
    asm volatile("ldmatrix.sync.aligned.m8n8.x4.shared.b16 {%0,%1,%2,%3}, [%4];"
        : "=r"(a[0]), "=r"(a[1]), "=r"(a[2]), "=r"(a[3]) : "r"(addr));
}
__device__ __forceinline__ void mma16816(float d[4], const uint32_t a[4], const uint32_t b[2]) {
    asm volatile("mma.sync.aligned.m16n8k16.row.col.f32.f16.f16.f32 "
        "{%0,%1,%2,%3}, {%4,%5,%6,%7}, {%8,%9}, {%0,%1,%2,%3};"
        : "+f"(d[0]), "+f"(d[1]), "+f"(d[2]), "+f"(d[3])
        : "r"(a[0]), "r"(a[1]), "r"(a[2]), "r"(a[3]), "r"(b[0]), "r"(b[1]));
}
__device__ __forceinline__ float mishf(float v) {
    return v * tanhf(log1pf(expf(v)));
}

// ---------------- pre-kernels ----------------
__global__ void style_kernel(const float* __restrict__ z,
                             const float* __restrict__ Wsty,
                             const float* __restrict__ bsty) {
    int b = blockIdx.x, i = threadIdx.x;
    __shared__ float zs[ZD];
    for (int k = threadIdx.x; k < ZD; k += blockDim.x) zs[k] = z[b * ZD + k];
    __syncthreads();
    float s = bsty[i];
    const float* wr = Wsty + i * ZD;
    #pragma unroll 4
    for (int k = 0; k < ZD; k++) s += zs[k] * wr[k];
    g_mod[b * CIN + i] = s + 1.0f;
}

__global__ void ssum_kernel(const float* __restrict__ w) {
    int o = blockIdx.x, i = threadIdx.x;
    const float* p = w + (o * CIN + i) * 9;
    float s = 0.f;
    #pragma unroll
    for (int k = 0; k < 9; k++) s += p[k] * p[k];
    g_S[o * CIN + i] = s;
}

__global__ void dscale_kernel() {
    int pair = blockIdx.x * 8 + (threadIdx.x >> 5);  // 0..4095
    int b = pair >> 7, o = pair & 127;
    int lane = threadIdx.x & 31;
    const float* m = g_mod + b * CIN;
    const float* s = g_S + o * CIN;
    float acc = 0.f;
    #pragma unroll
    for (int q = 0; q < 4; q++) {
        int i = q * 32 + lane;
        float mv = m[i];
        acc += mv * mv * s[i];
    }
    #pragma unroll
    for (int off = 16; off; off >>= 1) acc += __shfl_xor_sync(0xffffffffu, acc, off);
    if (lane == 0) g_dscale[pair] = rsqrtf(acc + EPSV);
}

__global__ void wcvt_kernel(const float* __restrict__ w) {
    int idx = blockIdx.x * 512 + threadIdx.x;      // 0..147455
    int j   = idx & 63;
    int oc  = (idx >> 6) & 127;
    int st  = idx >> 13;
    int ih  = st & 1;
    int tap = st >> 1;
    g_wh[idx] = __float2half_rn(w[(oc * CIN + (ih * 64 + j)) * 9 + tap]);
}

__global__ void xcvt_kernel(const float* __restrict__ x) {
    extern __shared__ float sm[];   // 128 * 133
    int b = blockIdx.x >> 7;
    int y = blockIdx.x & 127;
    #pragma unroll
    for (int i = 0; i < 16; i++) {
        int idx4 = i * 256 + threadIdx.x;
        int ic = idx4 >> 5;
        int x4 = (idx4 & 31) * 4;
        float4 v = *(const float4*)(x + (((size_t)(b * CIN + ic)) * HW + y) * HW + x4);
        float m = g_mod[b * CIN + ic];
        float* d = sm + ic * 133 + x4;
        d[0] = v.x * m; d[1] = v.y * m; d[2] = v.z * m; d[3] = v.w * m;
    }
    __syncthreads();
    int xc = threadIdx.x >> 1;
    int ih = threadIdx.x & 1;
    size_t o = (((size_t)(b * HW + y)) * HW + xc) * CIN + ih * 64;
    __half2* oh = (__half2*)(g_xh + o);
    #pragma unroll
    for (int q = 0; q < 32; q++) {
        float v0 = sm[(ih * 64 + 2 * q) * 133 + xc];
        float v1 = sm[(ih * 64 + 2 * q + 1) * 133 + xc];
        oh[q] = __floats2half2_rn(v0, v1);
    }
}

// ---------------- main conv: B-resident, 128 oc, fp16 mma.sync ----------------
// CTA = (b, 2 rows). D[128 oc x 256 px], K = 18 stages of 64 (ky-major).
// B resident: 4 input rows x 130 xc x 2 ih = 1040 rows x 128B (133120 B).
// A: 4-slot ring of 16KB stages.
#define OFF_A    133120
#define SM_TOTAL (133120 + 4 * 16384)   // 198656
#define SWZ(row, cb) ((cb) ^ (((row) & 7) << 4))

__global__ void __launch_bounds__(512, 1)
conv_mma_kernel(float* __restrict__ out) {
    extern __shared__ __align__(1024) unsigned char smem[];
    const uint32_t sb = smem_u32(smem);
    const int t   = threadIdx.x;
    const int wid = t >> 5;
    const int lid = t & 31;
    const int b   = blockIdx.x >> 6;
    const int y0  = (blockIdx.x & 63) << 1;

    const int oc0 = (wid & 3) * 32;   // warp oc block (32 of 128)
    const int n0  = (wid >> 2) * 64;  // warp px block (64 of 256)

    float d[2][8][4];
    #pragma unroll
    for (int mi = 0; mi < 2; mi++)
        #pragma unroll
        for (int ni = 0; ni < 8; ni++)
            #pragma unroll
            for (int j = 0; j < 4; j++) d[mi][ni][j] = 0.f;

    // per-thread B ldsm row bases (stage-invariant): pxr = py*130 + xc
    int pxr[4];
    #pragma unroll
    for (int nj = 0; nj < 4; nj++) {
        int brow = n0 + nj * 16 + ((lid >> 4) & 1) * 8 + (lid & 7);   // px 0..255
        pxr[nj] = (brow >> 7) * 130 + (brow & 127);
    }

    auto load_Brows = [&](int y_lo, int n_rows) {
        int rows  = n_rows * 130;
        int total = rows * 2 * 8;                  // cp16 ops
        for (int e = t; e < total; e += 512) {
            int g   = e & 7;
            int rl  = e >> 3;
            int ih  = (rl >= rows) ? 1 : 0;
            int rem = rl - ih * rows;
            int y   = y_lo + rem / 130;
            int xc  = rem % 130;
            int rid = ih * 520 + y * 130 + xc;
            int gy = y0 - 1 + y, gx = xc - 1;
            bool ok = (unsigned)gy < (unsigned)HW && (unsigned)gx < (unsigned)HW;
            const __half* src = g_xh
                + (((size_t)(b * HW + (ok ? gy : 0))) * HW + (ok ? gx : 0)) * CIN + ih * 64 + g * 8;
            cpasync16(sb + rid * 128 + SWZ(rid, g * 16), src, ok ? 16 : 0);
        }
    };

    auto load_A = [&](int s) {
        uint32_t bufo = OFF_A + (uint32_t)(s & 3) * 16384;
        #pragma unroll
        for (int i = 0; i < 2; i++) {
            int e = i * 512 + t;                   // 0..1023
            int row = e >> 3, g = e & 7;
            const __half* src = g_wh + (size_t)s * 8192 + row * 64 + g * 8;
            cpasync16(sb + bufo + row * 128 + SWZ(row, g * 16), src, 16);
        }
    };

    // prologue commits: C0 = B rows 0,1; C1 = A0; C2 = A1; C3 = B rows 2,3
    load_Brows(0, 2); CP_COMMIT();
    load_A(0);        CP_COMMIT();
    load_A(1);        CP_COMMIT();
    load_Brows(2, 2); CP_COMMIT();

    for (int s = 0; s < 18; s++) {
        // FIFO retirement: waiting for A_s also retires earlier B groups.
        if (s <= 15)      { CP_WAIT2(); }
        else if (s == 16) { CP_WAIT1(); }
        else              { CP_WAIT0(); }
        __syncthreads();
        if (s + 2 < 18) { load_A(s + 2); CP_COMMIT(); }

        const int tap = s >> 1;
        const int ih  = s & 1;
        const int ky  = tap / 3;
        const int kx  = tap - ky * 3;
        const int soff = ih * 520 + ky * 130 + kx;
        const uint32_t abase = sb + OFF_A + (uint32_t)(s & 3) * 16384;

        #pragma unroll
        for (int k16 = 0; k16 < 4; k16++) {
            uint32_t a[2][4];
            {
                const uint32_t acb = (uint32_t)k16 * 32 + ((lid >> 4) & 1) * 16;
                #pragma unroll
                for (int mi = 0; mi < 2; mi++) {
                    uint32_t row = oc0 + mi * 16 + (lid & 7) + ((lid >> 3) & 1) * 8;
                    ldsm_x4(a[mi], abase + row * 128 + SWZ(row, acb));
                }
            }
            const uint32_t bcb = (uint32_t)k16 * 32 + ((lid >> 3) & 1) * 16;
            #pragma unroll
            for (int nj = 0; nj < 4; nj++) {
                uint32_t rid = (uint32_t)(soff + pxr[nj]);
                uint32_t b4[4];
                ldsm_x4(b4, sb + rid * 128 + SWZ(rid, bcb));
                mma16816(d[0][2 * nj + 0], a[0], b4 + 0);
                mma16816(d[1][2 * nj + 0], a[1], b4 + 0);
                mma16816(d[0][2 * nj + 1], a[0], b4 + 2);
                mma16816(d[1][2 * nj + 1], a[1], b4 + 2);
            }
        }
    }
    __syncthreads();

    // ---- epilogue: dscale * mish, transpose through smem, write out ----
    float* ep = (float*)smem;        // [256 px][132]
    float dsc[2][2];
    #pragma unroll
    for (int mi = 0; mi < 2; mi++) {
        dsc[mi][0] = g_dscale[b * COUT + oc0 + mi * 16 + (lid >> 2)];
        dsc[mi][1] = g_dscale[b * COUT + oc0 + mi * 16 + (lid >> 2) + 8];
    }
    #pragma unroll
    for (int mi = 0; mi < 2; mi++) {
        #pragma unroll
        for (int ni = 0; ni < 8; ni++) {
            #pragma unroll
            for (int j = 0; j < 4; j++) {
                int oc = oc0 + mi * 16 + (lid >> 2) + ((j >> 1) ? 8 : 0);
                int px = n0 + ni * 8 + (lid & 3) * 2 + (j & 1);
                ep[px * 132 + oc] = mishf(d[mi][ni][j] * dsc[mi][(j >> 1)]);
            }
        }
    }
    __syncthreads();

    // 512 threads: oc2 = t&127, slot = t>>7 -> row r = slot>>1, half h = slot&1
    const int oc2  = t & 127;
    const int slot = t >> 7;
    const int r    = slot >> 1;
    const int h    = slot & 1;
    float* dst = out + (((size_t)(b * COUT + oc2)) * HW + (y0 + r)) * HW + h * 64;
    #pragma unroll
    for (int g = 0; g < 16; g++) {
        int px = r * 128 + h * 64 + g * 4;
        float4 v;
        v.x = ep[(px + 0) * 132 + oc2];
        v.y = ep[(px + 1) * 132 + oc2];
        v.z = ep[(px + 2) * 132 + oc2];
        v.w = ep[(px + 3) * 132 + oc2];
        *(float4*)(dst + g * 4) = v;
    }
}

// ---------------- launch ----------------
extern "C" void kernel_launch(void* const* d_in, const int* in_sizes, int n_in,
                              void* d_out, int out_size) {
    const float* x    = (const float*)d_in[0];
    const float* z    = (const float*)d_in[1];
    const float* w    = (const float*)d_in[2];
    const float* Wsty = (const float*)d_in[3];
    const float* bsty = (const float*)d_in[4];
    float* out = (float*)d_out;

    cudaFuncSetAttribute(conv_mma_kernel, cudaFuncAttributeMaxDynamicSharedMemorySize, SM_TOTAL);
    cudaFuncSetAttribute(xcvt_kernel, cudaFuncAttributeMaxDynamicSharedMemorySize, 128 * 133 * 4);

    style_kernel<<<B_, CIN>>>(z, Wsty, bsty);
    ssum_kernel<<<COUT, CIN>>>(w);
    dscale_kernel<<<512, 256>>>();
    wcvt_kernel<<<288, 512>>>(w);
    xcvt_kernel<<<B_ * HW, 256, 128 * 133 * 4>>>(x);
    conv_mma_kernel<<<B_ * 64, 512, SM_TOTAL>>>(out);
}